// round 9
// baseline (speedup 1.0000x reference)
#include <cuda_runtime.h>
#include <stdint.h>

#define HW      49
#define KP      56        // q padded (7 k-steps of 8)
#define MPAD    64        // p padded
#define CT      64        // c per CTA
#define CCOLS   512
#define THREADS 256
#define RA      68        // A row stride (floats), ==4 mod 32 -> conflict-free
#define RB2     68        // B2 row stride (uint2),  8t+2g bank pattern conflict-free

// smem: Afp[64*68] fp32 (17408 B) | B2[56*68] uint2 (30464 B); Y reuses B2 region
#define OFF_B2     (MPAD*RA)                     // float index where B2 starts
#define SMEM_BYTES (MPAD*RA*4 + KP*RB2*8)        // 47872

__device__ __forceinline__ uint32_t f2tf32(float v) {
    uint32_t r;
    asm("cvt.rna.tf32.f32 %0, %1;" : "=r"(r) : "f"(v));
    return r;
}

// exact hi/lo split: hi = tf32(v), lo = tf32(v - hi)
__device__ __forceinline__ uint2 split2(float v) {
    uint2 r;
    r.x = f2tf32(v);
    r.y = f2tf32(v - __uint_as_float(r.x));
    return r;
}

__device__ __forceinline__ void mma8(float* d, uint32_t a0, uint32_t a1, uint32_t a2, uint32_t a3,
                                     uint32_t b0, uint32_t b1) {
    asm volatile(
        "mma.sync.aligned.m16n8k8.row.col.f32.tf32.tf32.f32 "
        "{%0,%1,%2,%3}, {%4,%5,%6,%7}, {%8,%9}, {%0,%1,%2,%3};"
        : "+f"(d[0]), "+f"(d[1]), "+f"(d[2]), "+f"(d[3])
        : "r"(a0), "r"(a1), "r"(a2), "r"(a3), "r"(b0), "r"(b1));
}

__global__ __launch_bounds__(THREADS, 4)
void bmm_tf32_kernel(const float* __restrict__ x,
                     const float* __restrict__ attn,
                     const float* __restrict__ Dm,
                     const float* __restrict__ alpha,
                     float* __restrict__ out)
{
    extern __shared__ __align__(16) float sm[];
    float* Afp = sm;                       // [64][68] fp32, padded region zero
    uint2* B2  = (uint2*)(sm + OFF_B2);    // [56][68] (hi,lo) tf32 pairs
    float* Ysh = (float*)B2;               // Y[c*49+p] fp32 (12544 B) post-MMA

    const int n   = blockIdx.y;
    const int c0  = blockIdx.x * CT;
    const int tid = threadIdx.x;
    const int wid = tid >> 5;
    const int lid = tid & 31;
    const int g   = lid >> 2;     // groupID
    const int t   = lid & 3;      // thread-in-group

    // ---- stage A = attn[n] (49x49) fp32, zero-padded to 64x56 ----
    const float* An = attn + (size_t)n * HW * HW;
    for (int i = tid; i < MPAD * KP; i += THREADS) {        // 3584
        int p = i / KP, q = i - p * KP;
        Afp[p * RA + q] = (p < HW && q < HW) ? An[p * HW + q] : 0.f;
    }

    // ---- stage B = D[n][q][c0..c0+63] -> (hi,lo) tf32 pairs, rows q>=49 zero ----
    const float* Dn = Dm + (size_t)n * HW * CCOLS + c0;
    for (int i = tid; i < KP * (CT / 4); i += THREADS) {    // 896 quads
        int q = i >> 4, j = i & 15;                         // c = 4j
        float4 v = (q < HW) ? *(const float4*)(Dn + (size_t)q * CCOLS + 4 * j)
                            : make_float4(0.f, 0.f, 0.f, 0.f);
        uint2* dst = B2 + q * RB2 + 4 * j;
        uint2 s0 = split2(v.x), s1 = split2(v.y), s2 = split2(v.z), s3 = split2(v.w);
        *(uint4*)(dst)     = make_uint4(s0.x, s0.y, s1.x, s1.y);
        *(uint4*)(dst + 2) = make_uint4(s2.x, s2.y, s3.x, s3.y);
    }
    __syncthreads();

    // ---- mainloop: warp = (m-tile = wid&3, n-half = wid>>2); 4 n-tiles each ----
    const int mb = (wid & 3) * 16;
    const int nb = (wid >> 2) * 32;

    float acc[4][4];
#pragma unroll
    for (int nt = 0; nt < 4; ++nt)
#pragma unroll
        for (int d = 0; d < 4; ++d) acc[nt][d] = 0.f;

    const float* aB = Afp + (mb + g) * RA + t;
    const uint2* bB = B2 + t * RB2 + nb + g;

#pragma unroll
    for (int k0 = 0; k0 < 7; ++k0) {
        const int ka = k0 * 8;
        uint2 a0 = split2(aB[ka]);
        uint2 a1 = split2(aB[8 * RA + ka]);
        uint2 a2 = split2(aB[ka + 4]);
        uint2 a3 = split2(aB[8 * RA + ka + 4]);
#pragma unroll
        for (int nt = 0; nt < 4; ++nt) {
            uint2 b0 = bB[ka * RB2 + nt * 8];         // (hi,lo) in one LDS.64
            uint2 b1 = bB[(ka + 4) * RB2 + nt * 8];
            mma8(acc[nt], a0.x, a1.x, a2.x, a3.x, b0.x, b1.x);   // Ah*Bh
            mma8(acc[nt], a0.y, a1.y, a2.y, a3.y, b0.x, b1.x);   // Al*Bh
            mma8(acc[nt], a0.x, a1.x, a2.x, a3.x, b0.y, b1.y);   // Ah*Bl
        }
    }
    __syncthreads();     // all B reads done — safe to reuse region as Y

    // ---- scatter Y[c][p] into smem for contiguous gmem writes ----
    {
        const int p0 = mb + g, p1 = p0 + 8;
#pragma unroll
        for (int nt = 0; nt < 4; ++nt) {
            const int c = nb + nt * 8 + 2 * t;
            if (p0 < HW) {
                Ysh[c * HW + p0]       = acc[nt][0];
                Ysh[(c + 1) * HW + p0] = acc[nt][1];
            }
            if (p1 < HW) {
                Ysh[c * HW + p1]       = acc[nt][2];
                Ysh[(c + 1) * HW + p1] = acc[nt][3];
            }
        }
    }
    __syncthreads();

    // ---- residual epilogue: out[n, c0:c0+64, :] contiguous (3136 floats) ----
    const float  al_  = alpha[0];
    const size_t base = (size_t)n * CCOLS * HW + (size_t)c0 * HW;
    const float4* x4  = (const float4*)(x + base);
    const float4* y4  = (const float4*)Ysh;
    float4*       o4  = (float4*)(out + base);
    for (int i = tid; i < (CT * HW) / 4; i += THREADS) {   // 784
        float4 xv = x4[i], yv = y4[i], ov;
        ov.x = fmaf(al_, yv.x, xv.x);
        ov.y = fmaf(al_, yv.y, xv.y);
        ov.z = fmaf(al_, yv.z, xv.z);
        ov.w = fmaf(al_, yv.w, xv.w);
        o4[i] = ov;
    }
}

extern "C" void kernel_launch(void* const* d_in, const int* in_sizes, int n_in,
                              void* d_out, int out_size)
{
    const float* x     = (const float*)d_in[0];
    const float* attn  = (const float*)d_in[1];
    const float* Dm    = (const float*)d_in[2];
    const float* alpha = (const float*)d_in[3];
    float*       out   = (float*)d_out;

    cudaFuncSetAttribute(bmm_tf32_kernel, cudaFuncAttributeMaxDynamicSharedMemorySize, SMEM_BYTES);

    const int N = in_sizes[1] / (HW * HW);   // 2048
    dim3 grid(CCOLS / CT, N);                // (8, 2048)
    bmm_tf32_kernel<<<grid, THREADS, SMEM_BYTES>>>(x, attn, Dm, alpha, out);
}

// round 11
// speedup vs baseline: 1.5302x; 1.5302x over previous
#include <cuda_runtime.h>
#include <stdint.h>

#define HW      49
#define MPAD    64        // p padded
#define CT      64        // c per CTA
#define CCOLS   512
#define THREADS 256
#define SA      36        // A row stride in uint2 (36 ≡ 4 mod 16 -> conflict-free frags)
#define SB      68        // B row stride in uint2 (68 ≡ 4 mod 16 -> conflict-free frags)
#define NKP     32        // kpairs (K padded 49 -> 64)

// smem: Apk[64][36] uint2 (18432 B) | Bpk[32][68] uint2 (17408 B); Y reuses B
#define SMEM_BYTES (MPAD*SA*8 + NKP*SB*8)   // 35840

// split v into bf16 hi/lo (lo = bf16(v - float(hi))); no cuda_bf16.h needed
__device__ __forceinline__ void splitbf(float v, uint32_t& h, uint32_t& l) {
    unsigned short hs, ls;
    float hf;
    asm("cvt.rn.bf16.f32 %0, %1;" : "=h"(hs) : "f"(v));
    asm("cvt.f32.bf16 %0, %1;" : "=f"(hf) : "h"(hs));
    asm("cvt.rn.bf16.f32 %0, %1;" : "=h"(ls) : "f"(v - hf));
    h = hs; l = ls;
}

__device__ __forceinline__ void mma16(float* d, uint32_t a0, uint32_t a1, uint32_t a2, uint32_t a3,
                                      uint32_t b0, uint32_t b1) {
    asm volatile(
        "mma.sync.aligned.m16n8k16.row.col.f32.bf16.bf16.f32 "
        "{%0,%1,%2,%3}, {%4,%5,%6,%7}, {%8,%9}, {%0,%1,%2,%3};"
        : "+f"(d[0]), "+f"(d[1]), "+f"(d[2]), "+f"(d[3])
        : "r"(a0), "r"(a1), "r"(a2), "r"(a3), "r"(b0), "r"(b1));
}

__global__ __launch_bounds__(THREADS, 5)
void bmm_bf16_kernel(const float* __restrict__ x,
                     const float* __restrict__ attn,
                     const float* __restrict__ Dm,
                     const float* __restrict__ alpha,
                     float* __restrict__ out)
{
    extern __shared__ __align__(16) char sm[];
    uint2* Apk = (uint2*)sm;                       // [64 rows p][36] (hi-pair, lo-pair)
    uint2* Bpk = (uint2*)(sm + MPAD * SA * 8);     // [32 kpairs][68 cols c]
    float* Ysh = (float*)Bpk;                      // Y[c*49+p] (12544 B) post-MMA

    const int n   = blockIdx.y;
    const int c0  = blockIdx.x * CT;
    const int tid = threadIdx.x;
    const int wid = tid >> 5;
    const int lid = tid & 31;
    const int g   = lid >> 2;     // groupID
    const int t   = lid & 3;      // thread-in-group

    // ---- stage A = attn[n]: bf16 hi/lo k-pairs, zero-padded 64 x 32kp ----
    const float* An = attn + (size_t)n * HW * HW;
    for (int i = tid; i < MPAD * NKP; i += THREADS) {   // 2048
        int p = i >> 5, j = i & 31;                     // kpair j -> q = 2j, 2j+1
        float v0 = 0.f, v1 = 0.f;
        if (p < HW) {
            int q0 = 2 * j;
            if (q0 < HW)     v0 = An[p * HW + q0];
            if (q0 + 1 < HW) v1 = An[p * HW + q0 + 1];
        }
        uint32_t h0, l0, h1, l1;
        splitbf(v0, h0, l0);
        splitbf(v1, h1, l1);
        Apk[p * SA + j] = make_uint2(h0 | (h1 << 16), l0 | (l1 << 16));
    }

    // ---- stage B = D[n][q][c0..c0+63]: bf16 hi/lo k-pairs [kpair][c] ----
    const float* Dn = Dm + (size_t)n * HW * CCOLS + c0;
    for (int i = tid; i < NKP * (CT / 4); i += THREADS) {   // 512
        int j = i >> 4, c4 = i & 15;                        // kpair j, c = 4*c4
        int q0 = 2 * j;
        float4 u = (q0 < HW)     ? *(const float4*)(Dn + (size_t)q0 * CCOLS + 4 * c4)
                                 : make_float4(0.f, 0.f, 0.f, 0.f);
        float4 w = (q0 + 1 < HW) ? *(const float4*)(Dn + (size_t)(q0 + 1) * CCOLS + 4 * c4)
                                 : make_float4(0.f, 0.f, 0.f, 0.f);
        const float ue[4] = {u.x, u.y, u.z, u.w};
        const float we[4] = {w.x, w.y, w.z, w.w};
        uint2* dst = Bpk + j * SB + 4 * c4;
#pragma unroll
        for (int e = 0; e < 4; ++e) {
            uint32_t hu, lu, hw, lw;
            splitbf(ue[e], hu, lu);
            splitbf(we[e], hw, lw);
            dst[e] = make_uint2(hu | (hw << 16), lu | (lw << 16));  // (k even, k odd)
        }
    }
    __syncthreads();

    // ---- mainloop: warp = (m-tile = wid&3, n-half = wid>>2); 4 k16 steps ----
    const int mb = (wid & 3) * 16;
    const int nb = (wid >> 2) * 32;

    float acc[4][4];
#pragma unroll
    for (int nt = 0; nt < 4; ++nt)
#pragma unroll
        for (int d = 0; d < 4; ++d) acc[nt][d] = 0.f;

    const uint2* aP = Apk + (mb + g) * SA + t;
    const uint2* bP = Bpk + t * SB + nb + g;

#pragma unroll
    for (int ks = 0; ks < 4; ++ks) {               // kpairs 8ks .. 8ks+7
        uint2 A0 = aP[8 * ks];
        uint2 A1 = aP[8 * SA + 8 * ks];
        uint2 A2 = aP[8 * ks + 4];
        uint2 A3 = aP[8 * SA + 8 * ks + 4];
#pragma unroll
        for (int nt = 0; nt < 4; ++nt) {
            uint2 B0 = bP[(8 * ks) * SB + 8 * nt];
            uint2 B1 = bP[(8 * ks + 4) * SB + 8 * nt];
            mma16(acc[nt], A0.x, A1.x, A2.x, A3.x, B0.x, B1.x);   // Ah*Bh
            mma16(acc[nt], A0.y, A1.y, A2.y, A3.y, B0.x, B1.x);   // Al*Bh
            mma16(acc[nt], A0.x, A1.x, A2.x, A3.x, B0.y, B1.y);   // Ah*Bl
        }
    }
    __syncthreads();     // all B reads done — safe to reuse region as Y

    // ---- scatter Y[c][p] into smem for contiguous gmem writes ----
    {
        const int p0 = mb + g, p1 = p0 + 8;
#pragma unroll
        for (int nt = 0; nt < 4; ++nt) {
            const int c = nb + nt * 8 + 2 * t;
            if (p0 < HW) {
                Ysh[c * HW + p0]       = acc[nt][0];
                Ysh[(c + 1) * HW + p0] = acc[nt][1];
            }
            if (p1 < HW) {
                Ysh[c * HW + p1]       = acc[nt][2];
                Ysh[(c + 1) * HW + p1] = acc[nt][3];
            }
        }
    }
    __syncthreads();

    // ---- residual epilogue: out[n, c0:c0+64, :] contiguous (3136 floats) ----
    const float  al_  = alpha[0];
    const size_t base = (size_t)n * CCOLS * HW + (size_t)c0 * HW;
    const float4* x4  = (const float4*)(x + base);
    const float4* y4  = (const float4*)Ysh;
    float4*       o4  = (float4*)(out + base);
    for (int i = tid; i < (CT * HW) / 4; i += THREADS) {   // 784
        float4 xv = x4[i], yv = y4[i], ov;
        ov.x = fmaf(al_, yv.x, xv.x);
        ov.y = fmaf(al_, yv.y, xv.y);
        ov.z = fmaf(al_, yv.z, xv.z);
        ov.w = fmaf(al_, yv.w, xv.w);
        o4[i] = ov;
    }
}

extern "C" void kernel_launch(void* const* d_in, const int* in_sizes, int n_in,
                              void* d_out, int out_size)
{
    const float* x     = (const float*)d_in[0];
    const float* attn  = (const float*)d_in[1];
    const float* Dm    = (const float*)d_in[2];
    const float* alpha = (const float*)d_in[3];
    float*       out   = (float*)d_out;

    cudaFuncSetAttribute(bmm_bf16_kernel, cudaFuncAttributeMaxDynamicSharedMemorySize, SMEM_BYTES);

    const int N = in_sizes[1] / (HW * HW);   // 2048
    dim3 grid(CCOLS / CT, N);                // (8, 2048)
    bmm_bf16_kernel<<<grid, THREADS, SMEM_BYTES>>>(x, attn, Dm, alpha, out);
}